// round 1
// baseline (speedup 1.0000x reference)
#include <cuda_runtime.h>
#include <math.h>

#define NW   14
#define QDIM 16384
#define QBATCH 1024
#define NT   512

// ---------- host/device shared constant structures ----------
struct PassD {
    unsigned short combo[32];   // XOR offsets for orbit element k
    unsigned short rmask[5];    // logical-bit selection rows (parity masks)
    unsigned char  gate[5];     // index into coefficient table (layer*14 + wire)
    unsigned char  npos[10];    // non-pivot bit positions for orbit-rep enumeration
    unsigned char  k;           // gates in this pass
    unsigned char  pad;
};
struct QConsts {
    PassD pass[9];
    unsigned short meas[14];    // measurement parity masks (rows of T^-3)
};

// ---------- device kernel ----------
extern __shared__ float2 s_psi[];   // 16384 complex amplitudes (128 KB)

template<int K>
__device__ __forceinline__ void do_pass(float2* psi, const PassD& P,
                                        const float4* coef, int tid)
{
    constexpr int NE   = 1 << K;
    constexpr int NF   = NW - K;
    constexpr int NORB = 1 << NF;

    for (int o = tid; o < NORB; o += NT) {
        // build orbit representative: deposit o's bits into non-pivot positions
        unsigned yr = 0;
        #pragma unroll
        for (int i = 0; i < NF; i++)
            yr |= ((unsigned)(o >> i) & 1u) << P.npos[i];

        float2 e[NE];
        #pragma unroll
        for (int kk = 0; kk < NE; kk++)
            e[kk] = psi[yr ^ P.combo[kk]];

        #pragma unroll
        for (int j = 0; j < K; j++) {
            float4 c = coef[P.gate[j]];
            bool flip = (__popc(yr & (unsigned)P.rmask[j]) & 1);
            // U = [[a,b],[-b*,a*]]; flipped roles => a->a*, b->-b*
            float aR = c.x;
            float aI = flip ? -c.y : c.y;
            float bR = flip ? -c.z : c.z;
            float bI = c.w;
            #pragma unroll
            for (int kk = 0; kk < NE; kk++) {
                if (!((kk >> j) & 1)) {
                    int k1 = kk | (1 << j);
                    float x0r = e[kk].x, x0i = e[kk].y;
                    float x1r = e[k1].x, x1i = e[k1].y;
                    e[kk].x =  aR*x0r - aI*x0i + bR*x1r - bI*x1i;
                    e[kk].y =  aR*x0i + aI*x0r + bR*x1i + bI*x1r;
                    e[k1].x = -bR*x0r - bI*x0i + aR*x1r + aI*x1i;
                    e[k1].y =  bI*x0r - bR*x0i + aR*x1i - aI*x1r;
                }
            }
        }

        #pragma unroll
        for (int kk = 0; kk < NE; kk++)
            psi[yr ^ P.combo[kk]] = e[kk];
    }
}

__global__ void __launch_bounds__(NT, 1)
qsim_kernel(const float* __restrict__ state,
            const float* __restrict__ params,
            const float* __restrict__ head_w,
            const float* __restrict__ head_b,
            float* __restrict__ out,
            QConsts C)
{
    __shared__ float4 s_coef[42];        // fused-gate SU(2) coefficients
    __shared__ float  s_red[NT / 32][14];
    __shared__ float  s_feat[14];
    float2* psi = s_psi;

    const int tid = threadIdx.x;
    const int b   = blockIdx.x;

    // ---- load state (real -> complex) ----
    const float* st = state + (size_t)b * QDIM;
    #pragma unroll
    for (int i = 0; i < QDIM / NT; i++) {
        int idx = tid + i * NT;
        psi[idx] = make_float2(st[idx], 0.0f);
    }

    // ---- gate coefficients: U = RY(t2) * RX(t1) = [[a,b],[-b*,a*]] ----
    // a = c1c2 + i s1s2 ; b = -s2c1 - i c2s1
    if (tid < 42) {
        float tx = params[tid * 2 + 0] * 0.5f;
        float ty = params[tid * 2 + 1] * 0.5f;
        float s1, c1, s2, c2;
        sincosf(tx, &s1, &c1);
        sincosf(ty, &s2, &c2);
        s_coef[tid] = make_float4(c1 * c2, s1 * s2, -s2 * c1, -c2 * s1);
    }
    __syncthreads();

    // ---- 9 fused-gate passes (5+5+4 wires per layer, 3 layers) ----
    do_pass<5>(psi, C.pass[0], s_coef, tid); __syncthreads();
    do_pass<5>(psi, C.pass[1], s_coef, tid); __syncthreads();
    do_pass<4>(psi, C.pass[2], s_coef, tid); __syncthreads();
    do_pass<5>(psi, C.pass[3], s_coef, tid); __syncthreads();
    do_pass<5>(psi, C.pass[4], s_coef, tid); __syncthreads();
    do_pass<4>(psi, C.pass[5], s_coef, tid); __syncthreads();
    do_pass<5>(psi, C.pass[6], s_coef, tid); __syncthreads();
    do_pass<5>(psi, C.pass[7], s_coef, tid); __syncthreads();
    do_pass<4>(psi, C.pass[8], s_coef, tid); __syncthreads();

    // ---- measurement: probabilities + Walsh-Hadamard over high 5 bits ----
    float p[32];
    #pragma unroll
    for (int i = 0; i < 32; i++) {
        float2 a = psi[tid + (i << 9)];
        p[i] = a.x * a.x + a.y * a.y;
    }
    #pragma unroll
    for (int s = 0; s < 5; s++) {
        #pragma unroll
        for (int kk = 0; kk < 32; kk++) {
            if (!((kk >> s) & 1)) {
                int k1 = kk | (1 << s);
                float u = p[kk], v = p[k1];
                p[kk] = u + v;
                p[k1] = u - v;
            }
        }
    }

    const int warp = tid >> 5, lane = tid & 31;
    #pragma unroll
    for (int w = 0; w < 14; w++) {
        unsigned r = C.meas[w];
        float v = p[(r >> 9) & 31];
        v = (__popc(tid & r) & 1) ? -v : v;
        #pragma unroll
        for (int off = 16; off; off >>= 1)
            v += __shfl_xor_sync(0xffffffffu, v, off);
        if (lane == 0) s_red[warp][w] = v;
    }
    __syncthreads();

    if (tid < 14) {
        float f = 0.0f;
        #pragma unroll
        for (int q = 0; q < NT / 32; q++) f += s_red[q][tid];
        s_feat[tid] = f * head_w[tid];
    }
    __syncthreads();
    if (tid == 0) {
        float o = head_b[0];
        #pragma unroll
        for (int w = 0; w < 14; w++) o += s_feat[w];
        out[b] = o;
    }
}

// ---------- host: GF(2) circuit algebra ----------
static unsigned hc_apply(unsigned x, int c, int t) {
    int pc = 13 - c, pt = 13 - t;
    return x ^ (((x >> pc) & 1u) << pt);
}
// G = full CNOT ring as index map: new[x] = old[G x]
static unsigned G_fwd(unsigned x) {
    x = hc_apply(x, 13, 0);
    for (int w = 12; w >= 0; --w) x = hc_apply(x, w, w + 1);
    return x;
}
static unsigned G_inv(unsigned x) {
    for (int w = 0; w <= 12; ++w) x = hc_apply(x, w, w + 1);
    x = hc_apply(x, 13, 0);
    return x;
}

static void build_consts(QConsts& C) {
    unsigned v[4][14], r[4][14];
    for (int L = 0; L < 4; L++) {
        for (int w = 0; w < 14; w++) {
            unsigned e = 1u << (13 - w);
            for (int i = 0; i < L; i++) e = G_fwd(e);
            v[L][w] = e;                         // column p_w of G^L
        }
        unsigned cInv[14];
        for (int j = 0; j < 14; j++) {
            unsigned e = 1u << j;
            for (int i = 0; i < L; i++) e = G_inv(e);
            cInv[j] = e;                         // column j of G^-L
        }
        for (int w = 0; w < 14; w++) {
            unsigned rr = 0;
            for (int j = 0; j < 14; j++)
                rr |= ((cInv[j] >> (13 - w)) & 1u) << j;  // row p_w of G^-L
            r[L][w] = rr;
        }
    }

    const int gstart[3] = {0, 5, 10};
    const int gcnt[3]   = {5, 5, 4};
    for (int L = 0; L < 3; L++) {
        for (int g = 0; g < 3; g++) {
            PassD& P = C.pass[L * 3 + g];
            int K = gcnt[g], base = gstart[g];
            unsigned vs[5] = {0, 0, 0, 0, 0}, rs[5] = {0, 0, 0, 0, 0};
            for (int j = 0; j < K; j++) {
                vs[j] = v[L][base + j];
                rs[j] = r[L][base + j];
            }
            for (int kk = 0; kk < 32; kk++) {
                unsigned cb = 0;
                if (kk < (1 << K))
                    for (int j = 0; j < K; j++)
                        if ((kk >> j) & 1) cb ^= vs[j];
                P.combo[kk] = (unsigned short)cb;
            }
            for (int j = 0; j < 5; j++) {
                P.rmask[j] = (unsigned short)rs[j];
                P.gate[j]  = (unsigned char)((j < K) ? (L * 14 + base + j) : 0);
            }
            // forward Gaussian elimination: pick pivot bits for orbit reps
            bool ispiv[14] = {};
            unsigned red[5]; int piv[5];
            for (int j = 0; j < K; j++) {
                unsigned u = vs[j];
                for (int q = 0; q < j; q++)
                    if ((u >> piv[q]) & 1u) u ^= red[q];
                int hb = 13;
                while (hb > 0 && !((u >> hb) & 1u)) hb--;
                piv[j] = hb; red[j] = u; ispiv[hb] = true;
            }
            int idx = 0;
            for (int bpos = 0; bpos < 14; bpos++)
                if (!ispiv[bpos]) P.npos[idx++] = (unsigned char)bpos;
            while (idx < 10) P.npos[idx++] = 0;
            P.k = (unsigned char)K;
            P.pad = 0;
        }
    }
    for (int w = 0; w < 14; w++) C.meas[w] = (unsigned short)r[3][w];
}

// ---------- entry point ----------
extern "C" void kernel_launch(void* const* d_in, const int* in_sizes, int n_in,
                              void* d_out, int out_size)
{
    (void)in_sizes; (void)n_in; (void)out_size;
    const float* state  = (const float*)d_in[0];
    const float* params = (const float*)d_in[1];
    const float* head_w = (const float*)d_in[2];
    const float* head_b = (const float*)d_in[3];
    float* out = (float*)d_out;

    QConsts C;
    build_consts(C);

    static bool attr_done = false;
    if (!attr_done) {
        cudaFuncSetAttribute(qsim_kernel,
                             cudaFuncAttributeMaxDynamicSharedMemorySize,
                             QDIM * (int)sizeof(float2));
        attr_done = true;
    }

    qsim_kernel<<<QBATCH, NT, QDIM * sizeof(float2)>>>(
        state, params, head_w, head_b, out, C);
}

// round 3
// speedup vs baseline: 1.1889x; 1.1889x over previous
#include <cuda_runtime.h>
#include <math.h>

#define NW   14
#define QDIM 16384
#define QBATCH 1024
#define NT   1024
#define NPASS 12

// ---------- host/device shared constant structures ----------
struct PassD {
    unsigned short combo[16];   // XOR offsets for orbit element k (max NE=16)
    unsigned short rmask[4];    // logical-bit selection rows (parity masks)
    unsigned char  gate[4];     // index into coefficient table (layer*14 + wire)
    unsigned char  npos[11];    // non-pivot bit positions for orbit-rep enumeration
    unsigned char  k;           // gates in this pass
};
struct QConsts {
    PassD pass[NPASS];
    unsigned short meas[14];    // measurement parity masks (rows of T^-3)
};

// ---------- device kernel ----------
extern __shared__ float2 s_psi[];   // 16384 complex amplitudes (128 KB)

template<int K>
__device__ __forceinline__ void do_pass(float2* psi, const PassD& P,
                                        const float4* coef, int tid)
{
    constexpr int NE   = 1 << K;
    constexpr int NF   = NW - K;
    constexpr int NORB = 1 << NF;

    #pragma unroll
    for (int o = tid; o < NORB; o += NT) {
        // build orbit representative: deposit o's bits into non-pivot positions
        unsigned yr = 0;
        #pragma unroll
        for (int i = 0; i < NF; i++)
            yr |= ((unsigned)(o >> i) & 1u) << P.npos[i];

        float2 e[NE];
        #pragma unroll
        for (int kk = 0; kk < NE; kk++)
            e[kk] = psi[yr ^ P.combo[kk]];

        #pragma unroll
        for (int j = 0; j < K; j++) {
            float4 c = coef[P.gate[j]];
            bool flip = (__popc(yr & (unsigned)P.rmask[j]) & 1);
            // U = [[a,b],[-b*,a*]]; flipped roles => a->a*, b->-b*
            float aR = c.x;
            float aI = flip ? -c.y : c.y;
            float bR = flip ? -c.z : c.z;
            float bI = c.w;
            #pragma unroll
            for (int kk = 0; kk < NE; kk++) {
                if (!((kk >> j) & 1)) {
                    int k1 = kk | (1 << j);
                    float x0r = e[kk].x, x0i = e[kk].y;
                    float x1r = e[k1].x, x1i = e[k1].y;
                    e[kk].x =  aR*x0r - aI*x0i + bR*x1r - bI*x1i;
                    e[kk].y =  aR*x0i + aI*x0r + bR*x1i + bI*x1r;
                    e[k1].x = -bR*x0r - bI*x0i + aR*x1r + aI*x1i;
                    e[k1].y =  bI*x0r - bR*x0i + aR*x1i - aI*x1r;
                }
            }
        }

        #pragma unroll
        for (int kk = 0; kk < NE; kk++)
            psi[yr ^ P.combo[kk]] = e[kk];
    }
}

__global__ void __launch_bounds__(NT, 1)
qsim_kernel(const float* __restrict__ state,
            const float* __restrict__ params,
            const float* __restrict__ head_w,
            const float* __restrict__ head_b,
            float* __restrict__ out,
            QConsts C)
{
    __shared__ float4 s_coef[42];        // fused-gate SU(2) coefficients
    __shared__ float  s_red[NT / 32][14];
    __shared__ float  s_feat[14];
    float2* psi = s_psi;

    const int tid = threadIdx.x;
    const int b   = blockIdx.x;

    // ---- load state (real -> complex) ----
    const float* st = state + (size_t)b * QDIM;
    #pragma unroll
    for (int i = 0; i < QDIM / NT; i++) {
        int idx = tid + i * NT;
        psi[idx] = make_float2(st[idx], 0.0f);
    }

    // ---- gate coefficients: U = RY(t2) * RX(t1) = [[a,b],[-b*,a*]] ----
    // a = c1c2 + i s1s2 ; b = -s2c1 - i c2s1
    if (tid < 42) {
        float tx = params[tid * 2 + 0] * 0.5f;
        float ty = params[tid * 2 + 1] * 0.5f;
        float s1, c1, s2, c2;
        sincosf(tx, &s1, &c1);
        sincosf(ty, &s2, &c2);
        s_coef[tid] = make_float4(c1 * c2, s1 * s2, -s2 * c1, -c2 * s1);
    }
    __syncthreads();

    // ---- 12 fused-gate passes (4+4+3+3 wires per layer, 3 layers) ----
    #pragma unroll
    for (int L = 0; L < 3; L++) {
        do_pass<4>(psi, C.pass[L * 4 + 0], s_coef, tid); __syncthreads();
        do_pass<4>(psi, C.pass[L * 4 + 1], s_coef, tid); __syncthreads();
        do_pass<3>(psi, C.pass[L * 4 + 2], s_coef, tid); __syncthreads();
        do_pass<3>(psi, C.pass[L * 4 + 3], s_coef, tid); __syncthreads();
    }

    // ---- measurement: probabilities + Walsh-Hadamard over high 4 bits ----
    float p[16];
    #pragma unroll
    for (int i = 0; i < 16; i++) {
        float2 a = psi[tid + (i << 10)];
        p[i] = a.x * a.x + a.y * a.y;
    }
    #pragma unroll
    for (int s = 0; s < 4; s++) {
        #pragma unroll
        for (int kk = 0; kk < 16; kk++) {
            if (!((kk >> s) & 1)) {
                int k1 = kk | (1 << s);
                float u = p[kk], v = p[k1];
                p[kk] = u + v;
                p[k1] = u - v;
            }
        }
    }

    const int warp = tid >> 5, lane = tid & 31;
    #pragma unroll
    for (int w = 0; w < 14; w++) {
        unsigned r = C.meas[w];
        float v = p[(r >> 10) & 15];
        v = (__popc(tid & r) & 1) ? -v : v;
        #pragma unroll
        for (int off = 16; off; off >>= 1)
            v += __shfl_xor_sync(0xffffffffu, v, off);
        if (lane == 0) s_red[warp][w] = v;
    }
    __syncthreads();

    if (tid < 14) {
        float f = 0.0f;
        #pragma unroll
        for (int q = 0; q < NT / 32; q++) f += s_red[q][tid];
        s_feat[tid] = f * head_w[tid];
    }
    __syncthreads();
    if (tid == 0) {
        float o = head_b[0];
        #pragma unroll
        for (int w = 0; w < 14; w++) o += s_feat[w];
        out[b] = o;
    }
}

// ---------- host: GF(2) circuit algebra ----------
static unsigned hc_apply(unsigned x, int c, int t) {
    int pc = 13 - c, pt = 13 - t;
    return x ^ (((x >> pc) & 1u) << pt);
}
// G = full CNOT ring as index map: new[x] = old[G x]
static unsigned G_fwd(unsigned x) {
    x = hc_apply(x, 13, 0);
    for (int w = 12; w >= 0; --w) x = hc_apply(x, w, w + 1);
    return x;
}
static unsigned G_inv(unsigned x) {
    for (int w = 0; w <= 12; ++w) x = hc_apply(x, w, w + 1);
    x = hc_apply(x, 13, 0);
    return x;
}

static void build_consts(QConsts& C) {
    unsigned v[4][14], r[4][14];
    for (int L = 0; L < 4; L++) {
        for (int w = 0; w < 14; w++) {
            unsigned e = 1u << (13 - w);
            for (int i = 0; i < L; i++) e = G_fwd(e);
            v[L][w] = e;                         // column p_w of G^L
        }
        unsigned cInv[14];
        for (int j = 0; j < 14; j++) {
            unsigned e = 1u << j;
            for (int i = 0; i < L; i++) e = G_inv(e);
            cInv[j] = e;                         // column j of G^-L
        }
        for (int w = 0; w < 14; w++) {
            unsigned rr = 0;
            for (int j = 0; j < 14; j++)
                rr |= ((cInv[j] >> (13 - w)) & 1u) << j;  // row p_w of G^-L
            r[L][w] = rr;
        }
    }

    const int gstart[4] = {0, 4, 8, 11};
    const int gcnt[4]   = {4, 4, 3, 3};
    for (int L = 0; L < 3; L++) {
        for (int g = 0; g < 4; g++) {
            PassD& P = C.pass[L * 4 + g];
            int K = gcnt[g], base = gstart[g];
            unsigned vs[4] = {0, 0, 0, 0}, rs[4] = {0, 0, 0, 0};
            for (int j = 0; j < K; j++) {
                vs[j] = v[L][base + j];
                rs[j] = r[L][base + j];
            }
            for (int kk = 0; kk < 16; kk++) {
                unsigned cb = 0;
                if (kk < (1 << K))
                    for (int j = 0; j < K; j++)
                        if ((kk >> j) & 1) cb ^= vs[j];
                P.combo[kk] = (unsigned short)cb;
            }
            for (int j = 0; j < 4; j++) {
                P.rmask[j] = (unsigned short)((j < K) ? rs[j] : 0);
                P.gate[j]  = (unsigned char)((j < K) ? (L * 14 + base + j) : 0);
            }
            // forward Gaussian elimination: pick pivot bits for orbit reps
            bool ispiv[14] = {};
            unsigned red[4]; int piv[4];
            for (int j = 0; j < K; j++) {
                unsigned u = vs[j];
                for (int q = 0; q < j; q++)
                    if ((u >> piv[q]) & 1u) u ^= red[q];
                int hb = 13;
                while (hb > 0 && !((u >> hb) & 1u)) hb--;
                piv[j] = hb; red[j] = u; ispiv[hb] = true;
            }
            int idx = 0;
            for (int bpos = 0; bpos < 14; bpos++)
                if (!ispiv[bpos]) P.npos[idx++] = (unsigned char)bpos;
            while (idx < 11) P.npos[idx++] = 0;
            P.k = (unsigned char)K;
        }
    }
    for (int w = 0; w < 14; w++) C.meas[w] = (unsigned short)r[3][w];
}

// ---------- entry point ----------
extern "C" void kernel_launch(void* const* d_in, const int* in_sizes, int n_in,
                              void* d_out, int out_size)
{
    (void)in_sizes; (void)n_in; (void)out_size;
    const float* state  = (const float*)d_in[0];
    const float* params = (const float*)d_in[1];
    const float* head_w = (const float*)d_in[2];
    const float* head_b = (const float*)d_in[3];
    float* out = (float*)d_out;

    QConsts C;
    build_consts(C);

    static bool attr_done = false;
    if (!attr_done) {
        cudaFuncSetAttribute(qsim_kernel,
                             cudaFuncAttributeMaxDynamicSharedMemorySize,
                             QDIM * (int)sizeof(float2));
        attr_done = true;
    }

    qsim_kernel<<<QBATCH, NT, QDIM * sizeof(float2)>>>(
        state, params, head_w, head_b, out, C);
}

// round 5
// speedup vs baseline: 1.3108x; 1.1026x over previous
#include <cuda_runtime.h>
#include <math.h>

#define NW   14
#define QDIM 16384
#define QBATCH 1024
#define NT   1024

typedef unsigned long long ull;

// ================= compile-time GF(2) circuit algebra =================
struct PassC {
    unsigned combo[16];
    unsigned rmask[4];
    int      gate[4];
    int      K;
    int      ngrp;
    unsigned gmask[12];
    int      gshift[12];
};

__host__ __device__ constexpr unsigned hc(unsigned x, int c, int t) {
    int pc = 13 - c, pt = 13 - t;
    return x ^ (((x >> pc) & 1u) << pt);
}
__host__ __device__ constexpr unsigned Gf(unsigned x) {
    x = hc(x, 13, 0);
    for (int w = 12; w >= 0; --w) x = hc(x, w, w + 1);
    return x;
}
__host__ __device__ constexpr unsigned Gi(unsigned x) {
    for (int w = 0; w <= 12; ++w) x = hc(x, w, w + 1);
    x = hc(x, 13, 0);
    return x;
}
__host__ __device__ constexpr unsigned colV(int L, int w) {
    unsigned e = 1u << (13 - w);
    for (int i = 0; i < L; i++) e = Gf(e);
    return e;
}
__host__ __device__ constexpr unsigned rowR(int L, int w) {
    unsigned rr = 0;
    for (int j = 0; j < 14; j++) {
        unsigned e = 1u << j;
        for (int i = 0; i < L; i++) e = Gi(e);
        rr |= ((e >> (13 - w)) & 1u) << j;
    }
    return rr;
}

__host__ __device__ constexpr PassC build_pass(int pi) {
    PassC P = {};
    const int L = pi / 4, g = pi % 4;
    const int gstart[4] = {0, 4, 8, 11};
    const int gcnt[4]   = {4, 4, 3, 3};
    const int K = gcnt[g], base = gstart[g];

    unsigned vs[4] = {}, rs[4] = {};
    for (int j = 0; j < K; j++) {
        vs[j] = colV(L, base + j);
        rs[j] = rowR(L, base + j);
    }
    for (int kk = 0; kk < 16; kk++) {
        unsigned cb = 0;
        if (kk < (1 << K))
            for (int j = 0; j < K; j++)
                if ((kk >> j) & 1) cb ^= vs[j];
        P.combo[kk] = cb;
    }
    for (int j = 0; j < 4; j++) {
        P.rmask[j] = (j < K) ? rs[j] : 0u;
        P.gate[j]  = (j < K) ? (L * 14 + base + j) : 0;
    }
    // Gaussian elimination -> pivot bits; non-pivot bits host the orbit index
    bool ispiv[14] = {};
    unsigned red[4] = {}; int piv[4] = {};
    for (int j = 0; j < K; j++) {
        unsigned u = vs[j];
        for (int q = 0; q < j; q++)
            if ((u >> piv[q]) & 1u) u ^= red[q];
        int hb = 13;
        while (hb > 0 && !((u >> hb) & 1u)) hb--;
        piv[j] = hb; red[j] = u; ispiv[hb] = true;
    }
    int npos[14] = {}; int nf = 0;
    for (int b = 0; b < 14; b++)
        if (!ispiv[b]) npos[nf++] = b;
    // group bit-deposit into (mask, shift) runs with equal delta
    P.K = K; P.ngrp = 0;
    int i = 0;
    while (i < nf) {
        int d = npos[i] - i;
        unsigned m = 0; int j2 = i;
        while (j2 < nf && npos[j2] - j2 == d) { m |= 1u << j2; j2++; }
        P.gmask[P.ngrp]  = m;
        P.gshift[P.ngrp] = d;
        P.ngrp++;
        i = j2;
    }
    return P;
}

// ================= packed f32x2 helpers =================
__device__ __forceinline__ ull pk2(float lo, float hi) {
    ull r;
    asm("mov.b64 %0, {%1, %2};" : "=l"(r) : "f"(lo), "f"(hi));
    return r;
}
__device__ __forceinline__ ull swp(ull v) {
    unsigned lo, hi;
    asm("mov.b64 {%0, %1}, %2;" : "=r"(lo), "=r"(hi) : "l"(v));
    ull r;
    asm("mov.b64 %0, {%1, %2};" : "=l"(r) : "r"(hi), "r"(lo));
    return r;
}
__device__ __forceinline__ ull f2(ull a, ull b, ull c) {
    ull d;
    asm("fma.rn.f32x2 %0, %1, %2, %3;" : "=l"(d) : "l"(a), "l"(b), "l"(c));
    return d;
}
__device__ __forceinline__ ull m2(ull a, ull b) {
    ull d;
    asm("mul.rn.f32x2 %0, %1, %2;" : "=l"(d) : "l"(a), "l"(b));
    return d;
}

// ================= device kernel =================
extern __shared__ ull s_psi[];   // 16384 packed (re,im) amplitudes = 128 KB

template<int PI>
__device__ __forceinline__ void do_pass(ull* psiu, const float4 (*cf)[2], int tid)
{
    constexpr PassC P  = build_pass(PI);
    constexpr int K    = P.K;
    constexpr int NE   = 1 << K;
    constexpr int NORB = 1 << (NW - K);

    #pragma unroll
    for (int o = tid; o < NORB; o += NT) {
        unsigned yr = 0;
        #pragma unroll
        for (int g = 0; g < P.ngrp; g++)
            yr |= ((unsigned)o & P.gmask[g]) << P.gshift[g];

        ull e[NE];
        #pragma unroll
        for (int kk = 0; kk < NE; kk++)
            e[kk] = psiu[yr ^ P.combo[kk]];

        #pragma unroll
        for (int j = 0; j < K; j++) {
            const int flip = __popc(yr & P.rmask[j]) & 1;
            const float4 c = cf[P.gate[j]][flip];
            const float naI = -c.y, nbR = -c.z, nbI = -c.w;
            const ull A   = pk2(c.x, c.x);
            const ull Ai  = pk2(naI, c.y);
            const ull Ain = pk2(c.y, naI);
            const ull B   = pk2(c.z, c.z);
            const ull Bn  = pk2(nbR, nbR);
            const ull Bi  = pk2(nbI, c.w);
            #pragma unroll
            for (int kk = 0; kk < NE; kk++) {
                if (!((kk >> j) & 1)) {
                    const int k1 = kk | (1 << j);
                    const ull x0 = e[kk], x1 = e[k1];
                    const ull x0s = swp(x0), x1s = swp(x1);
                    // y0 = a*x0 + b*x1 ; y1 = -b*.x0 + a*.x1  (complex, packed re/im)
                    e[kk] = f2(A,  x0, f2(Ai, x0s, f2(B, x1, m2(Bi,  x1s))));
                    e[k1] = f2(Bn, x0, f2(Bi, x0s, f2(A, x1, m2(Ain, x1s))));
                }
            }
        }

        #pragma unroll
        for (int kk = 0; kk < NE; kk++)
            psiu[yr ^ P.combo[kk]] = e[kk];
    }
}

__global__ void __launch_bounds__(NT, 1)
qsim_kernel(const float* __restrict__ state,
            const float* __restrict__ params,
            const float* __restrict__ head_w,
            const float* __restrict__ head_b,
            float* __restrict__ out)
{
    __shared__ float4 s_cf[42][2];      // per-gate coefs, both flip variants
    __shared__ float  s_red[NT / 32][14];
    __shared__ float  s_feat[14];
    ull* psiu = s_psi;

    const int tid = threadIdx.x;
    const int b   = blockIdx.x;

    // ---- load state (real -> packed complex), vectorized ----
    const float4* st4 = (const float4*)(state + (size_t)b * QDIM);
    #pragma unroll
    for (int i = 0; i < QDIM / (4 * NT); i++) {
        const int v = tid + i * NT;
        const float4 x = st4[v];
        const int idx = v * 4;
        psiu[idx + 0] = (ull)__float_as_uint(x.x);
        psiu[idx + 1] = (ull)__float_as_uint(x.y);
        psiu[idx + 2] = (ull)__float_as_uint(x.z);
        psiu[idx + 3] = (ull)__float_as_uint(x.w);
    }

    // ---- gate coefficients: U = RY(t2) * RX(t1) = [[a,b],[-b*,a*]] ----
    if (tid < 42) {
        const float tx = params[tid * 2 + 0] * 0.5f;
        const float ty = params[tid * 2 + 1] * 0.5f;
        float s1, c1, s2, c2;
        sincosf(tx, &s1, &c1);
        sincosf(ty, &s2, &c2);
        const float aR = c1 * c2, aI = s1 * s2;
        const float bR = -s2 * c1, bI = -c2 * s1;
        s_cf[tid][0] = make_float4(aR,  aI,  bR, bI);
        s_cf[tid][1] = make_float4(aR, -aI, -bR, bI);
    }
    __syncthreads();

    // ---- 12 fused-gate passes (4+4+3+3 wires per layer, 3 layers) ----
    do_pass<0 >(psiu, s_cf, tid); __syncthreads();
    do_pass<1 >(psiu, s_cf, tid); __syncthreads();
    do_pass<2 >(psiu, s_cf, tid); __syncthreads();
    do_pass<3 >(psiu, s_cf, tid); __syncthreads();
    do_pass<4 >(psiu, s_cf, tid); __syncthreads();
    do_pass<5 >(psiu, s_cf, tid); __syncthreads();
    do_pass<6 >(psiu, s_cf, tid); __syncthreads();
    do_pass<7 >(psiu, s_cf, tid); __syncthreads();
    do_pass<8 >(psiu, s_cf, tid); __syncthreads();
    do_pass<9 >(psiu, s_cf, tid); __syncthreads();
    do_pass<10>(psiu, s_cf, tid); __syncthreads();
    do_pass<11>(psiu, s_cf, tid); __syncthreads();

    // ---- measurement: probabilities + Walsh-Hadamard over high 4 bits ----
    const float2* psf = (const float2*)psiu;
    float p[16];
    #pragma unroll
    for (int i = 0; i < 16; i++) {
        const float2 a = psf[tid + (i << 10)];
        p[i] = a.x * a.x + a.y * a.y;
    }
    #pragma unroll
    for (int s = 0; s < 4; s++) {
        #pragma unroll
        for (int kk = 0; kk < 16; kk++) {
            if (!((kk >> s) & 1)) {
                const int k1 = kk | (1 << s);
                const float u = p[kk], v = p[k1];
                p[kk] = u + v;
                p[k1] = u - v;
            }
        }
    }

    // measurement parity masks, fully compile-time (fold to immediates)
    constexpr unsigned MEAS[14] = {
        rowR(3, 0),  rowR(3, 1),  rowR(3, 2),  rowR(3, 3),
        rowR(3, 4),  rowR(3, 5),  rowR(3, 6),  rowR(3, 7),
        rowR(3, 8),  rowR(3, 9),  rowR(3, 10), rowR(3, 11),
        rowR(3, 12), rowR(3, 13)
    };

    const int warp = tid >> 5, lane = tid & 31;
    #pragma unroll
    for (int w = 0; w < 14; w++) {
        const unsigned r = MEAS[w];
        float v = p[(r >> 10) & 15];
        v = (__popc(tid & r) & 1) ? -v : v;
        #pragma unroll
        for (int off = 16; off; off >>= 1)
            v += __shfl_xor_sync(0xffffffffu, v, off);
        if (lane == 0) s_red[warp][w] = v;
    }
    __syncthreads();

    if (tid < 14) {
        float f = 0.0f;
        #pragma unroll
        for (int q = 0; q < NT / 32; q++) f += s_red[q][tid];
        s_feat[tid] = f * head_w[tid];
    }
    __syncthreads();
    if (tid == 0) {
        float o = head_b[0];
        #pragma unroll
        for (int w = 0; w < 14; w++) o += s_feat[w];
        out[b] = o;
    }
}

// ================= entry point =================
extern "C" void kernel_launch(void* const* d_in, const int* in_sizes, int n_in,
                              void* d_out, int out_size)
{
    (void)in_sizes; (void)n_in; (void)out_size;
    const float* state  = (const float*)d_in[0];
    const float* params = (const float*)d_in[1];
    const float* head_w = (const float*)d_in[2];
    const float* head_b = (const float*)d_in[3];
    float* out = (float*)d_out;

    static bool attr_done = false;
    if (!attr_done) {
        cudaFuncSetAttribute(qsim_kernel,
                             cudaFuncAttributeMaxDynamicSharedMemorySize,
                             QDIM * (int)sizeof(ull));
        attr_done = true;
    }

    qsim_kernel<<<QBATCH, NT, QDIM * sizeof(ull)>>>(
        state, params, head_w, head_b, out);
}

// round 6
// speedup vs baseline: 1.5320x; 1.1687x over previous
#include <cuda_runtime.h>
#include <math.h>

#define NW   14
#define QDIM 16384
#define QBATCH 1024
#define NT   1024

typedef unsigned long long ull;

// ================= compile-time GF(2) circuit algebra =================
__host__ __device__ constexpr unsigned sig(unsigned y) { return y ^ (y >> 7); }

struct PassC {
    unsigned combo[16];   // sigma-transformed XOR offsets
    unsigned rmask[4];    // parity masks on logical rep yr
    int      gate[4];
    int      K;
    int      ngrp;
    unsigned gmask[12];
    int      gshift[12];
};

__host__ __device__ constexpr unsigned hc(unsigned x, int c, int t) {
    int pc = 13 - c, pt = 13 - t;
    return x ^ (((x >> pc) & 1u) << pt);
}
__host__ __device__ constexpr unsigned Gf(unsigned x) {
    x = hc(x, 13, 0);
    for (int w = 12; w >= 0; --w) x = hc(x, w, w + 1);
    return x;
}
__host__ __device__ constexpr unsigned Gi(unsigned x) {
    for (int w = 0; w <= 12; ++w) x = hc(x, w, w + 1);
    x = hc(x, 13, 0);
    return x;
}
__host__ __device__ constexpr unsigned colV(int L, int w) {
    unsigned e = 1u << (13 - w);
    for (int i = 0; i < L; i++) e = Gf(e);
    return e;
}
__host__ __device__ constexpr unsigned rowR(int L, int w) {
    unsigned rr = 0;
    for (int j = 0; j < 14; j++) {
        unsigned e = 1u << j;
        for (int i = 0; i < L; i++) e = Gi(e);
        rr |= ((e >> (13 - w)) & 1u) << j;
    }
    return rr;
}

__host__ __device__ constexpr PassC build_pass(int pi) {
    PassC P = {};
    const int L = pi / 4, g = pi % 4;
    const int gstart[4] = {0, 4, 8, 11};
    const int gcnt[4]   = {4, 4, 3, 3};
    const int K = gcnt[g], base = gstart[g];

    unsigned vs[4] = {}, rs[4] = {};
    for (int j = 0; j < K; j++) {
        vs[j] = colV(L, base + j);
        rs[j] = rowR(L, base + j);
    }
    for (int kk = 0; kk < 16; kk++) {
        unsigned cb = 0;
        if (kk < (1 << K))
            for (int j = 0; j < K; j++)
                if ((kk >> j) & 1) cb ^= vs[j];
        P.combo[kk] = sig(cb);          // bake sigma into offsets
    }
    for (int j = 0; j < 4; j++) {
        P.rmask[j] = (j < K) ? rs[j] : 0u;
        P.gate[j]  = (j < K) ? (L * 14 + base + j) : 0;
    }
    // Gaussian elimination, high-bit pivots
    bool ispiv[14] = {};
    unsigned red[4] = {}; int piv[4] = {};
    for (int j = 0; j < K; j++) {
        unsigned u = vs[j];
        for (int q = 0; q < j; q++)
            if ((u >> piv[q]) & 1u) u ^= red[q];
        int hb = 13;
        while (hb > 0 && !((u >> hb) & 1u)) hb--;
        piv[j] = hb; red[j] = u; ispiv[hb] = true;
    }
    const int NF = 14 - K;
    bool used[14] = {};
    for (int b = 0; b < 14; b++) used[b] = ispiv[b];

    // lane-bit placement: half-warp lane bit t -> position t or t+7 so that
    // sigma(y) projects lane bits onto distinct bank bits 0..3 (conflict-free)
    int Pm[14] = {};
    for (int t = 0; t < 4; t++) {
        int pos = -1;
        if (!used[t]) pos = t;
        else if (!used[t + 7]) pos = t + 7;
        if (pos >= 0) { used[pos] = true; Pm[t] = pos; }
        else Pm[t] = -1;
    }
    for (int t = 0; t < 4; t++) {
        if (Pm[t] < 0) {
            for (int b = 0; b < 14; b++)
                if (!used[b]) { Pm[t] = b; used[b] = true; break; }
        }
    }
    int idx = 4;
    for (int b = 0; b < 14; b++)
        if (!used[b]) { Pm[idx++] = b; used[b] = true; }

    // run-compress (o bit i -> position Pm[i]) into (mask, shift) groups
    P.K = K; P.ngrp = 0;
    int i = 0;
    while (i < NF) {
        int d = Pm[i] - i;
        unsigned m = 0; int j2 = i;
        while (j2 < NF && Pm[j2] - j2 == d) { m |= 1u << j2; j2++; }
        P.gmask[P.ngrp]  = m;
        P.gshift[P.ngrp] = d;
        P.ngrp++;
        i = j2;
    }
    return P;
}

// ================= packed f32x2 helpers =================
__device__ __forceinline__ ull pk2(float lo, float hi) {
    ull r;
    asm("mov.b64 %0, {%1, %2};" : "=l"(r) : "f"(lo), "f"(hi));
    return r;
}
__device__ __forceinline__ ull swp(ull v) {
    unsigned lo, hi;
    asm("mov.b64 {%0, %1}, %2;" : "=r"(lo), "=r"(hi) : "l"(v));
    ull r;
    asm("mov.b64 %0, {%1, %2};" : "=l"(r) : "r"(hi), "r"(lo));
    return r;
}
__device__ __forceinline__ ull f2(ull a, ull b, ull c) {
    ull d;
    asm("fma.rn.f32x2 %0, %1, %2, %3;" : "=l"(d) : "l"(a), "l"(b), "l"(c));
    return d;
}
__device__ __forceinline__ ull m2(ull a, ull b) {
    ull d;
    asm("mul.rn.f32x2 %0, %1, %2;" : "=l"(d) : "l"(a), "l"(b));
    return d;
}

// ================= device kernel =================
extern __shared__ ull s_psi[];   // 16384 packed (re,im) amplitudes, sigma layout

template<int PI>
__device__ __forceinline__ void do_pass(ull* psiu, const ull* pk, int tid)
{
    constexpr PassC P  = build_pass(PI);
    constexpr int K    = P.K;
    constexpr int NE   = 1 << K;
    constexpr int NORB = 1 << (NW - K);

    #pragma unroll
    for (int o = tid; o < NORB; o += NT) {
        unsigned yr = 0;
        #pragma unroll
        for (int g = 0; g < P.ngrp; g++)
            yr |= ((unsigned)o & P.gmask[g]) << P.gshift[g];
        const unsigned syr = sig(yr);

        ull e[NE];
        #pragma unroll
        for (int kk = 0; kk < NE; kk++)
            e[kk] = psiu[syr ^ P.combo[kk]];

        #pragma unroll
        for (int j = 0; j < K; j++) {
            const int flip = __popc(yr & P.rmask[j]) & 1;
            const ull* cp = pk + (size_t)((P.gate[j] << 1) + flip) * 6;
            const ull A = cp[0], Ai = cp[1], Ain = cp[2];
            const ull B = cp[3], Bn = cp[4], Bi  = cp[5];
            #pragma unroll
            for (int kk = 0; kk < NE; kk++) {
                if (!((kk >> j) & 1)) {
                    const int k1 = kk | (1 << j);
                    const ull x0 = e[kk], x1 = e[k1];
                    const ull x0s = swp(x0), x1s = swp(x1);
                    e[kk] = f2(A,  x0, f2(Ai, x0s, f2(B, x1, m2(Bi,  x1s))));
                    e[k1] = f2(Bn, x0, f2(Bi, x0s, f2(A, x1, m2(Ain, x1s))));
                }
            }
        }

        #pragma unroll
        for (int kk = 0; kk < NE; kk++)
            psiu[syr ^ P.combo[kk]] = e[kk];
    }
}

__global__ void __launch_bounds__(NT, 1)
qsim_kernel(const float* __restrict__ state,
            const float* __restrict__ params,
            const float* __restrict__ head_w,
            const float* __restrict__ head_b,
            float* __restrict__ out)
{
    __shared__ ull   s_pk[84 * 6];      // packed coef ulls per (gate, flip)
    __shared__ float s_red[NT / 32][14];
    __shared__ float s_feat[14];
    ull* psiu = s_psi;

    const int tid = threadIdx.x;
    const int b   = blockIdx.x;

    // ---- load state (real -> packed complex), sigma layout ----
    const float4* st4 = (const float4*)(state + (size_t)b * QDIM);
    #pragma unroll
    for (int i = 0; i < QDIM / (4 * NT); i++) {
        const int v = tid + i * NT;
        const float4 x = st4[v];
        const unsigned idx = (unsigned)v * 4u;
        psiu[sig(idx + 0)] = (ull)__float_as_uint(x.x);
        psiu[sig(idx + 1)] = (ull)__float_as_uint(x.y);
        psiu[sig(idx + 2)] = (ull)__float_as_uint(x.z);
        psiu[sig(idx + 3)] = (ull)__float_as_uint(x.w);
    }

    // ---- packed gate coefficients: U = RY(t2)*RX(t1) = [[a,b],[-b*,a*]] ----
    if (tid < 84) {
        const int g = tid >> 1, f = tid & 1;
        const float tx = params[g * 2 + 0] * 0.5f;
        const float ty = params[g * 2 + 1] * 0.5f;
        float s1, c1, s2, c2;
        sincosf(tx, &s1, &c1);
        sincosf(ty, &s2, &c2);
        float aR = c1 * c2, aI = s1 * s2;
        float bR = -s2 * c1, bI = -c2 * s1;
        if (f) { aI = -aI; bR = -bR; }
        ull* q = s_pk + tid * 6;
        q[0] = pk2(aR, aR);
        q[1] = pk2(-aI, aI);
        q[2] = pk2(aI, -aI);
        q[3] = pk2(bR, bR);
        q[4] = pk2(-bR, -bR);
        q[5] = pk2(-bI, bI);
    }
    __syncthreads();

    // ---- 12 fused-gate passes (4+4+3+3 wires per layer, 3 layers) ----
    do_pass<0 >(psiu, s_pk, tid); __syncthreads();
    do_pass<1 >(psiu, s_pk, tid); __syncthreads();
    do_pass<2 >(psiu, s_pk, tid); __syncthreads();
    do_pass<3 >(psiu, s_pk, tid); __syncthreads();
    do_pass<4 >(psiu, s_pk, tid); __syncthreads();
    do_pass<5 >(psiu, s_pk, tid); __syncthreads();
    do_pass<6 >(psiu, s_pk, tid); __syncthreads();
    do_pass<7 >(psiu, s_pk, tid); __syncthreads();
    do_pass<8 >(psiu, s_pk, tid); __syncthreads();
    do_pass<9 >(psiu, s_pk, tid); __syncthreads();
    do_pass<10>(psiu, s_pk, tid); __syncthreads();
    do_pass<11>(psiu, s_pk, tid); __syncthreads();

    // ---- measurement: probabilities + Walsh-Hadamard over high 4 bits ----
    const float2* psf = (const float2*)psiu;
    float p[16];
    #pragma unroll
    for (int i = 0; i < 16; i++) {
        const unsigned y = (unsigned)tid + ((unsigned)i << 10);
        const float2 a = psf[sig(y)];
        p[i] = a.x * a.x + a.y * a.y;
    }
    #pragma unroll
    for (int s = 0; s < 4; s++) {
        #pragma unroll
        for (int kk = 0; kk < 16; kk++) {
            if (!((kk >> s) & 1)) {
                const int k1 = kk | (1 << s);
                const float u = p[kk], v = p[k1];
                p[kk] = u + v;
                p[k1] = u - v;
            }
        }
    }

    constexpr unsigned MEAS[14] = {
        rowR(3, 0),  rowR(3, 1),  rowR(3, 2),  rowR(3, 3),
        rowR(3, 4),  rowR(3, 5),  rowR(3, 6),  rowR(3, 7),
        rowR(3, 8),  rowR(3, 9),  rowR(3, 10), rowR(3, 11),
        rowR(3, 12), rowR(3, 13)
    };

    const int warp = tid >> 5, lane = tid & 31;
    #pragma unroll
    for (int w = 0; w < 14; w++) {
        const unsigned r = MEAS[w];
        float v = p[(r >> 10) & 15];
        v = (__popc(tid & r) & 1) ? -v : v;
        #pragma unroll
        for (int off = 16; off; off >>= 1)
            v += __shfl_xor_sync(0xffffffffu, v, off);
        if (lane == 0) s_red[warp][w] = v;
    }
    __syncthreads();

    if (tid < 14) {
        float f = 0.0f;
        #pragma unroll
        for (int q = 0; q < NT / 32; q++) f += s_red[q][tid];
        s_feat[tid] = f * head_w[tid];
    }
    __syncthreads();
    if (tid == 0) {
        float o = head_b[0];
        #pragma unroll
        for (int w = 0; w < 14; w++) o += s_feat[w];
        out[b] = o;
    }
}

// ================= entry point =================
extern "C" void kernel_launch(void* const* d_in, const int* in_sizes, int n_in,
                              void* d_out, int out_size)
{
    (void)in_sizes; (void)n_in; (void)out_size;
    const float* state  = (const float*)d_in[0];
    const float* params = (const float*)d_in[1];
    const float* head_w = (const float*)d_in[2];
    const float* head_b = (const float*)d_in[3];
    float* out = (float*)d_out;

    static bool attr_done = false;
    if (!attr_done) {
        cudaFuncSetAttribute(qsim_kernel,
                             cudaFuncAttributeMaxDynamicSharedMemorySize,
                             QDIM * (int)sizeof(ull));
        attr_done = true;
    }

    qsim_kernel<<<QBATCH, NT, QDIM * sizeof(ull)>>>(
        state, params, head_w, head_b, out);
}